// round 11
// baseline (speedup 1.0000x reference)
#include <cuda_runtime.h>

#define NB     8
#define NATOM  512
#define NFEAT  42
#define NNEIGH 100
#define NPT    256
#define NH1    64
#define NH2    32

#define FT     384            // force kernel threads (divisible by 3!)
#define NPAIR  (NNEIGH*NFEAT) // 4200
#define NQ     (NPAIR*3/4)    // 3150 float4s per atom tile

// scratch for dE (input gradient), computed by ei_kernel, consumed by force_kernel
__device__ float g_dE[NB * NATOM * NFEAT];

// fast tanh: clamped exp-based, well within 1e-3 rel-err budget
__device__ __forceinline__ float fast_tanh(float x)
{
    x = fminf(15.0f, fmaxf(-15.0f, x));
    const float e = __expf(2.0f * x);
    return __fdividef(e - 1.0f, e + 1.0f);
}

// ---------------------------------------------------------------------------
// Kernel 1: per-atom MLP forward + backward, warp-per-atom.
// ---------------------------------------------------------------------------
__global__ __launch_bounds__(256) void ei_kernel(
    const float* __restrict__ image,
    const float* __restrict__ W0, const float* __restrict__ b0,
    const float* __restrict__ W1, const float* __restrict__ b1,
    const float* __restrict__ W2, const float* __restrict__ b2,
    float* __restrict__ out)
{
    __shared__ float sW0[NH1 * 43];
    __shared__ float sW1[NH2 * 65];
    __shared__ float sW2[NH2];
    __shared__ float sb0[NH1];
    __shared__ float sb1[NH2];
    __shared__ float sb2v;
    __shared__ float sx [8][NFEAT];
    __shared__ float sh1[8][NH1];
    __shared__ float sg2[8][NH2];
    __shared__ float sg1[8][NH1];

    const int tid = threadIdx.x;
    const int w   = tid >> 5;
    const int l   = tid & 31;

    const int base = blockIdx.x * 8;
    const int b    = base / NATOM;
    const int a0   = base % NATOM;
    const int t    = a0 / NPT;

    for (int i = tid; i < NH1 * NFEAT; i += 256) {
        int r = i / NFEAT, c = i - r * NFEAT;
        sW0[r * 43 + c] = W0[t * NH1 * NFEAT + i];
    }
    for (int i = tid; i < NH2 * NH1; i += 256) {
        int r = i >> 6, c = i & 63;
        sW1[r * 65 + c] = W1[t * NH2 * NH1 + i];
    }
    if (tid < NH2) sW2[tid] = W2[t * NH2 + tid];
    if (tid < NH1) sb0[tid] = b0[t * NH1 + tid];
    if (tid < NH2) sb1[tid] = b1[t * NH2 + tid];
    if (tid == 0)  sb2v = b2[t];
    __syncthreads();

    const int gidx = b * NATOM + (a0 + w);

    if (l < NFEAT)      sx[w][l]      = image[gidx * NFEAT + l];
    if (l < NFEAT - 32) sx[w][32 + l] = image[gidx * NFEAT + 32 + l];
    __syncwarp();

    float s1 = sb0[l], s2 = sb0[32 + l];
    #pragma unroll
    for (int f = 0; f < NFEAT; f++) {
        const float xv = sx[w][f];
        s1 += xv * sW0[l * 43 + f];
        s2 += xv * sW0[(32 + l) * 43 + f];
    }
    const float h1a = fast_tanh(s1), h1b = fast_tanh(s2);
    sh1[w][l] = h1a; sh1[w][32 + l] = h1b;
    __syncwarp();

    float s = sb1[l];
    #pragma unroll
    for (int i = 0; i < NH1; i++) s += sh1[w][i] * sW1[l * 65 + i];
    const float h2 = fast_tanh(s);
    const float w2v = sW2[l];
    sg2[w][l] = w2v * (1.0f - h2 * h2);

    float v = h2 * w2v;
    #pragma unroll
    for (int o = 16; o > 0; o >>= 1) v += __shfl_down_sync(0xffffffffu, v, o);
    if (l == 0) out[8 + gidx] = v + sb2v;
    __syncwarp();

    float t1 = 0.0f, t2 = 0.0f;
    #pragma unroll
    for (int j = 0; j < NH2; j++) {
        const float gv = sg2[w][j];
        t1 += gv * sW1[j * 65 + l];
        t2 += gv * sW1[j * 65 + 32 + l];
    }
    sg1[w][l]      = t1 * (1.0f - h1a * h1a);
    sg1[w][32 + l] = t2 * (1.0f - h1b * h1b);
    __syncwarp();

    const int c2 = (l < NFEAT - 32) ? (32 + l) : 0;
    float d1 = 0.0f, d2 = 0.0f;
    #pragma unroll
    for (int i = 0; i < NH1; i++) {
        const float gv = sg1[w][i];
        d1 += gv * sW0[i * 43 + l];
        d2 += gv * sW0[i * 43 + c2];
    }
    if (l < NFEAT)      g_dE[gidx * NFEAT + l]      = d1;
    if (l < NFEAT - 32) g_dE[gidx * NFEAT + 32 + l] = d2;
}

// ---------------------------------------------------------------------------
// Kernel 2: Force. 4096 blocks x 384 threads (384 % 3 == 0 is load-bearing).
// R7 structure (uniform loop, no prefetch -> ~32 regs, high occupancy) with
// the multiplier fetch reduced to 2 LDS.32 (sg[m], sg[m+1]) + 2 data SELs:
// o0 = 0 and o3 = 1 always; only slots 1,2 depend on phase = tid%3.
// dfeat read with __ldcs (streamed once; keep L2 for the dE gather).
// k(s) = (phase+s)%3 -> slot accumulators map to (x,y,z) once at the end.
// Blocks 0..7 also fold in the Etot reduction (deterministic order).
// ---------------------------------------------------------------------------
__global__ __launch_bounds__(FT) void force_kernel(
    const float* __restrict__ dfeat,
    const int* __restrict__ neighbor,
    float* __restrict__ out)
{
    __shared__ float sg[NPAIR];          // 4200 gathered dE values
    __shared__ int   sn[NNEIGH];
    __shared__ float red[FT / 32][3];
    __shared__ float sred[8];

    const int tid  = threadIdx.x;
    const int gidx = blockIdx.x;             // b*NATOM + a
    const int b    = gidx / NATOM;

    if (tid < NNEIGH)
        sn[tid] = neighbor[gidx * NNEIGH + tid];

    // fused Etot partial (blocks 0..7, first 256 threads): deterministic
    if (gidx < NB && tid < 256) {
        const float* Ei = out + 8 + gidx * NATOM;
        float v = Ei[tid] + Ei[tid + 256];
        #pragma unroll
        for (int o = 16; o > 0; o >>= 1) v += __shfl_down_sync(0xffffffffu, v, o);
        if ((tid & 31) == 0) sred[tid >> 5] = v;
    }
    __syncthreads();

    // Gather: one L2 load per (n,f) pair; index 0 -> zero pad row
    for (int p = tid; p < NPAIR; p += FT) {
        const int n = p / NFEAT;
        const int f = p - n * NFEAT;
        const int j = sn[n];
        sg[p] = j ? g_dE[(b * NATOM + (j - 1)) * NFEAT + f] : 0.0f;
    }
    __syncthreads();

    if (gidx < NB && tid == 0) {
        float s = 0.0f;
        #pragma unroll
        for (int ww = 0; ww < 8; ww++) s += sred[ww];
        out[gidx] = s;
    }

    const float4* __restrict__ df = (const float4*)(dfeat + (long)gidx * (NPAIR * 3));

    const int  phase = tid % 3;              // == q mod 3 for all iterations
    const int  m0    = (4 * tid) / 3;
    const bool s1hi  = (phase == 2);         // slot1 uses gB iff phase==2
    const bool s2hi  = (phase >= 1);         // slot2 uses gB iff phase>=1

    float a0 = 0.0f, a1 = 0.0f, a2 = 0.0f, a3 = 0.0f;

    // 8 unconditional iterations: q = tid + it*384 <= 3071 < 3150
    #pragma unroll
    for (int it = 0; it < 8; it++) {
        const int q = tid + it * FT;
        const int m = m0 + it * 512;
        const float4 v = __ldcs(df + q);
        const float gA = sg[m];
        const float gB = sg[m + 1];
        a0 += gA * v.x;
        a1 += (s1hi ? gB : gA) * v.y;
        a2 += (s2hi ? gB : gA) * v.z;
        a3 += gB * v.w;
    }
    // tail: it = 8, valid iff tid < 3150 - 3072 = 78
    if (tid < NQ - 8 * FT) {
        const int q = tid + 8 * FT;
        const int m = m0 + 8 * 512;           // m0 max 102 -> 4198+1 < 4200
        const float4 v = __ldcs(df + q);
        const float gA = sg[m];
        const float gB = sg[m + 1];
        a0 += gA * v.x;
        a1 += (s1hi ? gB : gA) * v.y;
        a2 += (s2hi ? gB : gA) * v.z;
        a3 += gB * v.w;
    }

    // map slot accumulators to (x,y,z):  k(s) = (phase + s) mod 3
    float ax, ay, az;
    if (phase == 0)      { ax = a0 + a3; ay = a1;      az = a2;      }
    else if (phase == 1) { ax = a2;      ay = a0 + a3; az = a1;      }
    else                 { ax = a1;      ay = a2;      az = a0 + a3; }

    #pragma unroll
    for (int o = 16; o > 0; o >>= 1) {
        ax += __shfl_down_sync(0xffffffffu, ax, o);
        ay += __shfl_down_sync(0xffffffffu, ay, o);
        az += __shfl_down_sync(0xffffffffu, az, o);
    }
    const int w = tid >> 5, l = tid & 31;
    if (l == 0) { red[w][0] = ax; red[w][1] = ay; red[w][2] = az; }
    __syncthreads();
    if (tid < 3) {
        float s = 0.0f;
        #pragma unroll
        for (int ww = 0; ww < FT / 32; ww++) s += red[ww][tid];
        out[8 + NB * NATOM + gidx * 3 + tid] = s;
    }
}

// ---------------------------------------------------------------------------
// Launch: out layout = [Etot(8) | Ei(4096) | Force(12288)] = 16392 f32
// ---------------------------------------------------------------------------
extern "C" void kernel_launch(void* const* d_in, const int* in_sizes, int n_in,
                              void* d_out, int out_size)
{
    const float* image    = (const float*)d_in[0];
    const float* dfeat    = (const float*)d_in[1];
    const int*   neighbor = (const int*)d_in[2];
    // d_in[3] = natoms_img (unused)
    const float* W0 = (const float*)d_in[4];
    const float* b0 = (const float*)d_in[5];
    const float* W1 = (const float*)d_in[6];
    const float* b1 = (const float*)d_in[7];
    const float* W2 = (const float*)d_in[8];
    const float* b2 = (const float*)d_in[9];
    float* out = (float*)d_out;

    ei_kernel<<<(NB * NATOM) / 8, 256>>>(image, W0, b0, W1, b1, W2, b2, out);
    force_kernel<<<NB * NATOM, FT>>>(dfeat, neighbor, out);
}

// round 12
// speedup vs baseline: 1.3308x; 1.3308x over previous
#include <cuda_runtime.h>

#define NB     8
#define NATOM  512
#define NFEAT  42
#define NNEIGH 100
#define NPT    256
#define NH1    64
#define NH2    32

#define FT     384            // force kernel threads (divisible by 3!)
#define NPAIR  (NNEIGH*NFEAT) // 4200
#define NQ     (NPAIR*3/4)    // 3150 float4s per atom tile

// scratch for dE (input gradient), computed by ei_kernel, consumed by force_kernel
__device__ float g_dE[NB * NATOM * NFEAT];

// fast tanh: clamped exp-based, well within 1e-3 rel-err budget
__device__ __forceinline__ float fast_tanh(float x)
{
    x = fminf(15.0f, fmaxf(-15.0f, x));
    const float e = __expf(2.0f * x);
    return __fdividef(e - 1.0f, e + 1.0f);
}

// ---------------------------------------------------------------------------
// Kernel 1: per-atom MLP forward + backward, TWO atoms per warp.
// Grid: 256 blocks x 256 threads = 8 warps/block, 16 atoms/block.
// Warp w handles atoms (base+w) and (base+w+8); every weight LDS now feeds
// FMAs for two atoms, cutting weight-smem traffic per atom ~40%.
// ---------------------------------------------------------------------------
__global__ __launch_bounds__(256) void ei_kernel(
    const float* __restrict__ image,
    const float* __restrict__ W0, const float* __restrict__ b0,
    const float* __restrict__ W1, const float* __restrict__ b1,
    const float* __restrict__ W2, const float* __restrict__ b2,
    float* __restrict__ out)
{
    __shared__ float sW0[NH1 * 43];
    __shared__ float sW1[NH2 * 65];
    __shared__ float sW2[NH2];
    __shared__ float sb0[NH1];
    __shared__ float sb1[NH2];
    __shared__ float sb2v;
    __shared__ float sx [16][NFEAT];
    __shared__ float sh1[16][NH1];
    __shared__ float sg2[16][NH2];
    __shared__ float sg1[16][NH1];

    const int tid = threadIdx.x;
    const int w   = tid >> 5;        // warp id: atoms w and w+8
    const int l   = tid & 31;

    const int base = blockIdx.x * 16;        // never crosses the type boundary
    const int b    = base / NATOM;
    const int a0   = base % NATOM;
    const int t    = a0 / NPT;

    for (int i = tid; i < NH1 * NFEAT; i += 256) {
        int r = i / NFEAT, c = i - r * NFEAT;
        sW0[r * 43 + c] = W0[t * NH1 * NFEAT + i];
    }
    for (int i = tid; i < NH2 * NH1; i += 256) {
        int r = i >> 6, c = i & 63;
        sW1[r * 65 + c] = W1[t * NH2 * NH1 + i];
    }
    if (tid < NH2) sW2[tid] = W2[t * NH2 + tid];
    if (tid < NH1) sb0[tid] = b0[t * NH1 + tid];
    if (tid < NH2) sb1[tid] = b1[t * NH2 + tid];
    if (tid == 0)  sb2v = b2[t];
    __syncthreads();

    const int gA = b * NATOM + (a0 + w);          // atom A
    const int gB = gA + 8;                        // atom B
    const int wB = w + 8;

    // load x for both atoms
    if (l < NFEAT) {
        sx[w][l]  = image[gA * NFEAT + l];
        sx[wB][l] = image[gB * NFEAT + l];
    }
    if (l < NFEAT - 32) {
        sx[w][32 + l]  = image[gA * NFEAT + 32 + l];
        sx[wB][32 + l] = image[gB * NFEAT + 32 + l];
    }
    __syncwarp();

    // h1 = tanh(W0 x + b0): neurons l and l+32, both atoms
    float s1a = sb0[l], s2a = sb0[32 + l];
    float s1b = s1a,    s2b = s2a;
    #pragma unroll
    for (int f = 0; f < NFEAT; f++) {
        const float w0a = sW0[l * 43 + f];
        const float w0b = sW0[(32 + l) * 43 + f];
        const float xa  = sx[w][f];
        const float xb  = sx[wB][f];
        s1a += xa * w0a;  s2a += xa * w0b;
        s1b += xb * w0a;  s2b += xb * w0b;
    }
    const float h1aA = fast_tanh(s1a), h1bA = fast_tanh(s2a);
    const float h1aB = fast_tanh(s1b), h1bB = fast_tanh(s2b);
    sh1[w][l]  = h1aA; sh1[w][32 + l]  = h1bA;
    sh1[wB][l] = h1aB; sh1[wB][32 + l] = h1bB;
    __syncwarp();

    // h2 = tanh(W1 h1 + b1), g2 = W2 .* (1 - h2^2): one neuron, both atoms
    float sA = sb1[l], sB = sb1[l];
    #pragma unroll
    for (int i = 0; i < NH1; i++) {
        const float w1 = sW1[l * 65 + i];
        sA += sh1[w][i]  * w1;
        sB += sh1[wB][i] * w1;
    }
    const float h2A = fast_tanh(sA), h2B = fast_tanh(sB);
    const float w2v = sW2[l];
    sg2[w][l]  = w2v * (1.0f - h2A * h2A);
    sg2[wB][l] = w2v * (1.0f - h2B * h2B);

    // Ei = W2 . h2 + b2 (warp reduce, both atoms)
    float vA = h2A * w2v, vB = h2B * w2v;
    #pragma unroll
    for (int o = 16; o > 0; o >>= 1) {
        vA += __shfl_down_sync(0xffffffffu, vA, o);
        vB += __shfl_down_sync(0xffffffffu, vB, o);
    }
    if (l == 0) { out[8 + gA] = vA + sb2v; out[8 + gB] = vB + sb2v; }
    __syncwarp();

    // g1 = (W1^T g2) .* (1 - h1^2): entries l and l+32, both atoms
    float t1a = 0.0f, t2a = 0.0f, t1b = 0.0f, t2b = 0.0f;
    #pragma unroll
    for (int j = 0; j < NH2; j++) {
        const float w1a = sW1[j * 65 + l];
        const float w1b = sW1[j * 65 + 32 + l];
        const float ga  = sg2[w][j];
        const float gb  = sg2[wB][j];
        t1a += ga * w1a;  t2a += ga * w1b;
        t1b += gb * w1a;  t2b += gb * w1b;
    }
    sg1[w][l]       = t1a * (1.0f - h1aA * h1aA);
    sg1[w][32 + l]  = t2a * (1.0f - h1bA * h1bA);
    sg1[wB][l]      = t1b * (1.0f - h1aB * h1aB);
    sg1[wB][32 + l] = t2b * (1.0f - h1bB * h1bB);
    __syncwarp();

    // dx = W0^T g1: features l and 32+l (guarded), both atoms
    const int c2 = (l < NFEAT - 32) ? (32 + l) : 0;
    float d1a = 0.0f, d2a = 0.0f, d1b = 0.0f, d2b = 0.0f;
    #pragma unroll
    for (int i = 0; i < NH1; i++) {
        const float w0a = sW0[i * 43 + l];
        const float w0b = sW0[i * 43 + c2];
        const float ga  = sg1[w][i];
        const float gb  = sg1[wB][i];
        d1a += ga * w0a;  d2a += ga * w0b;
        d1b += gb * w0a;  d2b += gb * w0b;
    }
    if (l < NFEAT) {
        g_dE[gA * NFEAT + l] = d1a;
        g_dE[gB * NFEAT + l] = d1b;
    }
    if (l < NFEAT - 32) {
        g_dE[gA * NFEAT + 32 + l] = d2a;
        g_dE[gB * NFEAT + 32 + l] = d2b;
    }
}

// ---------------------------------------------------------------------------
// Kernel 2: Force. 4096 blocks x 384 threads (384 % 3 == 0 is load-bearing).
// Uniform loop, no prefetch (~32 regs, high occupancy), plain LDG (no .cs —
// R11 showed the evict-first hint degrades effective DRAM bandwidth).
// Multiplier fetch: 2 LDS.32 (sg[m], sg[m+1]) + 2 data SELs; o0=0, o3=1
// always, only slots 1,2 depend on phase = tid%3.
// k(s) = (phase+s)%3 -> slot accumulators map to (x,y,z) once at the end.
// Blocks 0..7 also fold in the Etot reduction (deterministic order).
// ---------------------------------------------------------------------------
__global__ __launch_bounds__(FT) void force_kernel(
    const float* __restrict__ dfeat,
    const int* __restrict__ neighbor,
    float* __restrict__ out)
{
    __shared__ float sg[NPAIR];          // 4200 gathered dE values
    __shared__ int   sn[NNEIGH];
    __shared__ float red[FT / 32][3];
    __shared__ float sred[8];

    const int tid  = threadIdx.x;
    const int gidx = blockIdx.x;             // b*NATOM + a
    const int b    = gidx / NATOM;

    if (tid < NNEIGH)
        sn[tid] = neighbor[gidx * NNEIGH + tid];

    // fused Etot partial (blocks 0..7, first 256 threads): deterministic
    if (gidx < NB && tid < 256) {
        const float* Ei = out + 8 + gidx * NATOM;
        float v = Ei[tid] + Ei[tid + 256];
        #pragma unroll
        for (int o = 16; o > 0; o >>= 1) v += __shfl_down_sync(0xffffffffu, v, o);
        if ((tid & 31) == 0) sred[tid >> 5] = v;
    }
    __syncthreads();

    // Gather: one L2 load per (n,f) pair; index 0 -> zero pad row
    for (int p = tid; p < NPAIR; p += FT) {
        const int n = p / NFEAT;
        const int f = p - n * NFEAT;
        const int j = sn[n];
        sg[p] = j ? g_dE[(b * NATOM + (j - 1)) * NFEAT + f] : 0.0f;
    }
    __syncthreads();

    if (gidx < NB && tid == 0) {
        float s = 0.0f;
        #pragma unroll
        for (int ww = 0; ww < 8; ww++) s += sred[ww];
        out[gidx] = s;
    }

    const float4* __restrict__ df = (const float4*)(dfeat + (long)gidx * (NPAIR * 3));

    const int  phase = tid % 3;              // == q mod 3 for all iterations
    const int  m0    = (4 * tid) / 3;
    const bool s1hi  = (phase == 2);         // slot1 uses gB iff phase==2
    const bool s2hi  = (phase >= 1);         // slot2 uses gB iff phase>=1

    float a0 = 0.0f, a1 = 0.0f, a2 = 0.0f, a3 = 0.0f;

    // 8 unconditional iterations: q = tid + it*384 <= 3071 < 3150
    #pragma unroll
    for (int it = 0; it < 8; it++) {
        const int q = tid + it * FT;
        const int m = m0 + it * 512;
        const float4 v = df[q];
        const float gA = sg[m];
        const float gB = sg[m + 1];
        a0 += gA * v.x;
        a1 += (s1hi ? gB : gA) * v.y;
        a2 += (s2hi ? gB : gA) * v.z;
        a3 += gB * v.w;
    }
    // tail: it = 8, valid iff tid < 3150 - 3072 = 78
    if (tid < NQ - 8 * FT) {
        const int q = tid + 8 * FT;
        const int m = m0 + 8 * 512;           // m0 max 102 -> 4198+1 < 4200
        const float4 v = df[q];
        const float gA = sg[m];
        const float gB = sg[m + 1];
        a0 += gA * v.x;
        a1 += (s1hi ? gB : gA) * v.y;
        a2 += (s2hi ? gB : gA) * v.z;
        a3 += gB * v.w;
    }

    // map slot accumulators to (x,y,z):  k(s) = (phase + s) mod 3
    float ax, ay, az;
    if (phase == 0)      { ax = a0 + a3; ay = a1;      az = a2;      }
    else if (phase == 1) { ax = a2;      ay = a0 + a3; az = a1;      }
    else                 { ax = a1;      ay = a2;      az = a0 + a3; }

    #pragma unroll
    for (int o = 16; o > 0; o >>= 1) {
        ax += __shfl_down_sync(0xffffffffu, ax, o);
        ay += __shfl_down_sync(0xffffffffu, ay, o);
        az += __shfl_down_sync(0xffffffffu, az, o);
    }
    const int w = tid >> 5, l = tid & 31;
    if (l == 0) { red[w][0] = ax; red[w][1] = ay; red[w][2] = az; }
    __syncthreads();
    if (tid < 3) {
        float s = 0.0f;
        #pragma unroll
        for (int ww = 0; ww < FT / 32; ww++) s += red[ww][tid];
        out[8 + NB * NATOM + gidx * 3 + tid] = s;
    }
}

// ---------------------------------------------------------------------------
// Launch: out layout = [Etot(8) | Ei(4096) | Force(12288)] = 16392 f32
// ---------------------------------------------------------------------------
extern "C" void kernel_launch(void* const* d_in, const int* in_sizes, int n_in,
                              void* d_out, int out_size)
{
    const float* image    = (const float*)d_in[0];
    const float* dfeat    = (const float*)d_in[1];
    const int*   neighbor = (const int*)d_in[2];
    // d_in[3] = natoms_img (unused)
    const float* W0 = (const float*)d_in[4];
    const float* b0 = (const float*)d_in[5];
    const float* W1 = (const float*)d_in[6];
    const float* b1 = (const float*)d_in[7];
    const float* W2 = (const float*)d_in[8];
    const float* b2 = (const float*)d_in[9];
    float* out = (float*)d_out;

    ei_kernel<<<(NB * NATOM) / 16, 256>>>(image, W0, b0, W1, b1, W2, b2, out);
    force_kernel<<<NB * NATOM, FT>>>(dfeat, neighbor, out);
}